// round 7
// baseline (speedup 1.0000x reference)
#include <cuda_runtime.h>
#include <cuda_bf16.h>

#define T_      512
#define B_      512
#define EMB_    32
#define HID_    32
#define G4_     128   // 4*HID
#define FF_     16
#define NCLS_   7
#define VOCAB_  1000

// ---------------- scratch (static device memory) ----------------------------
__device__ float g_tab[VOCAB_ * G4_];          // 512 KB: xg per vocab entry
__device__ float g_hs[(size_t)T_ * B_ * HID_]; // 32 MB hidden states

// ---------------- fast math --------------------------------------------------
__device__ __forceinline__ float ex2f(float x) {
    float r; asm("ex2.approx.f32 %0, %1;" : "=f"(r) : "f"(x)); return r;
}
__device__ __forceinline__ float rcpf(float x) {
    float r; asm("rcp.approx.f32 %0, %1;" : "=f"(r) : "f"(x)); return r;
}
__device__ __forceinline__ float sigm_f(float x) {
    return rcpf(1.0f + ex2f(-1.4426950408889634f * x));
}
__device__ __forceinline__ float tanh_f(float x) {
    return fmaf(2.0f, rcpf(1.0f + ex2f(-2.8853900817779268f * x)), -1.0f);
}

// ---------------- packed f32x2 helpers ---------------------------------------
typedef unsigned long long u64;
__device__ __forceinline__ u64 pack2(float lo, float hi) {
    u64 d; asm("mov.b64 %0, {%1, %2};" : "=l"(d) : "f"(lo), "f"(hi)); return d;
}
__device__ __forceinline__ void unpack2(u64 v, float& lo, float& hi) {
    asm("mov.b64 {%0, %1}, %2;" : "=f"(lo), "=f"(hi) : "l"(v));
}
__device__ __forceinline__ u64 ffma2(u64 a, u64 b, u64 c) {
    u64 d; asm("fma.rn.f32x2 %0, %1, %2, %3;" : "=l"(d) : "l"(a), "l"(b), "l"(c));
    return d;
}
__device__ __forceinline__ u64 fadd2(u64 a, u64 b) {
    u64 d; asm("add.rn.f32x2 %0, %1, %2;" : "=l"(d) : "l"(a), "l"(b)); return d;
}

// ---- token dtype sniff: int64 tokens (<1000) have zero high words ----------
__device__ __forceinline__ bool x_is_i64(const int* __restrict__ x32) {
    return (x32[1] | x32[3] | x32[5] | x32[7] | x32[9]) == 0;
}
__device__ __forceinline__ int get_tok(const int* __restrict__ x32,
                                       bool i64, int idx) {
    return x32[i64 ? (idx << 1) : idx];
}

// ---------------- K1: gate table --------------------------------------------
__global__ __launch_bounds__(128) void k_table(
    const float* __restrict__ emb, const float* __restrict__ W_ih,
    const float* __restrict__ b_ih, const float* __restrict__ b_hh)
{
    __shared__ float e_sh[EMB_];
    const int v = blockIdx.x;
    const int row = threadIdx.x;          // 0..127
    if (row < EMB_) e_sh[row] = emb[v * EMB_ + row];
    __syncthreads();
    float acc = b_ih[row] + b_hh[row];
#pragma unroll
    for (int e = 0; e < EMB_; ++e)
        acc = fmaf(W_ih[row * EMB_ + e], e_sh[e], acc);
    g_tab[v * G4_ + row] = acc;
}

// ---------------- K2: LSTM, f32x2 gate-pair packing + LDS-broadcast h -------
// Warp per batch element. lane k owns h[k], c[k].
// Packed accumulators: {a_i, a_f} and {a_g, a_o}.
// h is stored duplicated {h,h} in shared; read as uniform LDS.128 broadcasts.
__global__ __launch_bounds__(128) void k_lstm4(
    const int* __restrict__ x, const float* __restrict__ W_hh)
{
    __shared__ int tok_s[4][T_];                       // 8 KB
    __shared__ __align__(16) u64 h_sh2[4][2][HID_];    // 2 KB, {h,h} pairs

    const int tid  = threadIdx.x;
    const int wid  = tid >> 5;
    const int lane = tid & 31;
    const int b    = blockIdx.x * 4 + wid;
    const bool i64 = x_is_i64(x);

    // one-time token staging
    for (int i = lane; i < T_; i += 32)
        tok_s[wid][i] = get_tok(x, i64, i * B_ + b);

    // packed recurrent weights: Wif[j] = {Wi[j], Wf[j]}, Wgo[j] = {Wg[j], Wo[j]}
    u64 Wif[HID_], Wgo[HID_];
#pragma unroll
    for (int j = 0; j < HID_; ++j) {
        Wif[j] = pack2(W_hh[(0 * HID_ + lane) * HID_ + j],
                       W_hh[(1 * HID_ + lane) * HID_ + j]);
        Wgo[j] = pack2(W_hh[(2 * HID_ + lane) * HID_ + j],
                       W_hh[(3 * HID_ + lane) * HID_ + j]);
    }

    h_sh2[wid][0][lane] = 0ull;            // {0,0}
    float c = 0.0f;
    int p = 0;
    __syncwarp();

    // prefetch packed xg for t=0
    int tk = tok_s[wid][0];
    u64 xif_n = pack2(g_tab[tk * G4_ + 0 * HID_ + lane],
                      g_tab[tk * G4_ + 1 * HID_ + lane]);
    u64 xgo_n = pack2(g_tab[tk * G4_ + 2 * HID_ + lane],
                      g_tab[tk * G4_ + 3 * HID_ + lane]);

    for (int t = 0; t < T_; ++t) {
        // 4 split accumulator chains (even/odd j) saturate the FMA pipe
        u64 aif0 = xif_n, aif1 = 0ull;
        u64 ago0 = xgo_n, ago1 = 0ull;

        // prefetch next step's xg
        tk = tok_s[wid][(t + 1) & (T_ - 1)];
        xif_n = pack2(g_tab[tk * G4_ + 0 * HID_ + lane],
                      g_tab[tk * G4_ + 1 * HID_ + lane]);
        xgo_n = pack2(g_tab[tk * G4_ + 2 * HID_ + lane],
                      g_tab[tk * G4_ + 3 * HID_ + lane]);

        // recurrence: 16 uniform LDS.128 broadcasts deliver {h_j,h_j} pairs
        const ulonglong2* hp = reinterpret_cast<const ulonglong2*>(h_sh2[wid][p]);
#pragma unroll
        for (int q = 0; q < HID_ / 2; ++q) {
            const ulonglong2 hh = hp[q];           // {h_2q,h_2q},{h_2q+1,h_2q+1}
            aif0 = ffma2(Wif[2 * q + 0], hh.x, aif0);
            ago0 = ffma2(Wgo[2 * q + 0], hh.x, ago0);
            aif1 = ffma2(Wif[2 * q + 1], hh.y, aif1);
            ago1 = ffma2(Wgo[2 * q + 1], hh.y, ago1);
        }
        const u64 aif = fadd2(aif0, aif1);
        const u64 ago = fadd2(ago0, ago1);

        float ai, af, ag, ao;
        unpack2(aif, ai, af);
        unpack2(ago, ag, ao);

        const float ig = sigm_f(ai);
        const float fg = sigm_f(af);
        const float gg = tanh_f(ag);
        const float og = sigm_f(ao);
        c = fmaf(fg, c, ig * gg);
        const float h = og * tanh_f(c);

        h_sh2[wid][1 - p][lane] = pack2(h, h);
        g_hs[((size_t)t * B_ + b) * HID_ + lane] = h;  // coalesced 128B/warp
        __syncwarp();
        p ^= 1;
    }
}

// ---------------- K3: FF + logits -------------------------------------------
__global__ __launch_bounds__(256) void k_ff2(
    const float* __restrict__ W1, const float* __restrict__ b1,
    const float* __restrict__ W2, const float* __restrict__ b2,
    float* __restrict__ out)
{
    const int r = blockIdx.x * 256 + threadIdx.x;      // flat row t*B+b
    float hv[HID_];
    const float4* hp = reinterpret_cast<const float4*>(&g_hs[(size_t)r * HID_]);
#pragma unroll
    for (int q = 0; q < HID_ / 4; ++q) {
        const float4 v = hp[q];
        hv[q * 4 + 0] = v.x; hv[q * 4 + 1] = v.y;
        hv[q * 4 + 2] = v.z; hv[q * 4 + 3] = v.w;
    }
    float z[FF_];
#pragma unroll
    for (int f = 0; f < FF_; ++f) {
        float a = b1[f];
#pragma unroll
        for (int j = 0; j < HID_; ++j)
            a = fmaf(W1[f * HID_ + j], hv[j], a);
        z[f] = fmaxf(a, 0.0f);
    }
#pragma unroll
    for (int cl = 0; cl < NCLS_; ++cl) {
        float a = b2[cl];
#pragma unroll
        for (int f = 0; f < FF_; ++f)
            a = fmaf(W2[cl * FF_ + f], z[f], a);
        out[(size_t)r * NCLS_ + cl] = a;
    }
}

// ---------------- K4: softmax over T, row-wise threads, in place ------------
// block = batch b; 256 threads; thread owns rows t=tid and t=tid+256 (7 floats
// each, contiguous 28B). Per-class reduce: warp shfl + 8-warp shared combine.
__global__ __launch_bounds__(256) void k_softmax2(float* __restrict__ out)
{
    __shared__ float red[NCLS_][8];
    const int b    = blockIdx.x;
    const int tid  = threadIdx.x;
    const int lane = tid & 31;
    const int w    = tid >> 5;

    float v0[NCLS_], v1[NCLS_];
    {
        const float* p0 = &out[((size_t)(tid      ) * B_ + b) * NCLS_];
        const float* p1 = &out[((size_t)(tid + 256) * B_ + b) * NCLS_];
#pragma unroll
        for (int cl = 0; cl < NCLS_; ++cl) { v0[cl] = p0[cl]; v1[cl] = p1[cl]; }
    }

    // ---- max over t per class ----
    float mx[NCLS_];
#pragma unroll
    for (int cl = 0; cl < NCLS_; ++cl) {
        float m = fmaxf(v0[cl], v1[cl]);
#pragma unroll
        for (int s = 16; s > 0; s >>= 1)
            m = fmaxf(m, __shfl_xor_sync(0xffffffffu, m, s));
        if (lane == 0) red[cl][w] = m;
        mx[cl] = m;                       // placeholder; finalized below
    }
    __syncthreads();
#pragma unroll
    for (int cl = 0; cl < NCLS_; ++cl) {
        float m = red[cl][0];
#pragma unroll
        for (int q = 1; q < 8; ++q) m = fmaxf(m, red[cl][q]);
        mx[cl] = m;
    }
    __syncthreads();                      // red reuse barrier

    // ---- exp + sum over t per class ----
    float sm[NCLS_];
#pragma unroll
    for (int cl = 0; cl < NCLS_; ++cl) {
        v0[cl] = ex2f(1.4426950408889634f * (v0[cl] - mx[cl]));
        v1[cl] = ex2f(1.4426950408889634f * (v1[cl] - mx[cl]));
        float s = v0[cl] + v1[cl];
#pragma unroll
        for (int q = 16; q > 0; q >>= 1)
            s += __shfl_xor_sync(0xffffffffu, s, q);
        if (lane == 0) red[cl][w] = s;
        sm[cl] = s;
    }
    __syncthreads();
#pragma unroll
    for (int cl = 0; cl < NCLS_; ++cl) {
        float s = red[cl][0];
#pragma unroll
        for (int q = 1; q < 8; ++q) s += red[cl][q];
        sm[cl] = 1.0f / s;
    }

    {
        float* p0 = &out[((size_t)(tid      ) * B_ + b) * NCLS_];
        float* p1 = &out[((size_t)(tid + 256) * B_ + b) * NCLS_];
#pragma unroll
        for (int cl = 0; cl < NCLS_; ++cl) {
            p0[cl] = v0[cl] * sm[cl];
            p1[cl] = v1[cl] * sm[cl];
        }
    }
}

// ---------------- launch: bind by size + infer W-pair orientation -----------
extern "C" void kernel_launch(void* const* d_in, const int* in_sizes, int n_in,
                              void* d_out, int out_size)
{
    const int*   x    = nullptr;
    const float* emb  = nullptr;
    const float* Wp0  = nullptr;
    const float* Wp1  = nullptr;
    const float* b_ih = nullptr;
    const float* b_hh = nullptr;
    const float* W1   = nullptr;
    const float* b1   = nullptr;
    const float* W2   = nullptr;
    const float* b2   = nullptr;
    int idx_W1 = -1, idx_Wp0 = -1;

    for (int i = 0; i < n_in; ++i) {
        const int s = in_sizes[i];
        const void* p = d_in[i];
        switch (s) {
            case T_ * B_:
            case 2 * T_ * B_:
                if (!x) x = (const int*)p;
                break;
            case VOCAB_ * EMB_:
                emb = (const float*)p; break;
            case G4_ * EMB_:
                if (!Wp0) { Wp0 = (const float*)p; idx_Wp0 = i; }
                else      { Wp1 = (const float*)p; }
                break;
            case G4_:
                if (!b_ih) b_ih = (const float*)p; else b_hh = (const float*)p;
                break;
            case FF_ * HID_:
                W1 = (const float*)p; idx_W1 = i; break;
            case FF_:
                b1 = (const float*)p; break;
            case NCLS_ * FF_:
                W2 = (const float*)p; break;
            case NCLS_:
                b2 = (const float*)p; break;
            default: break;
        }
    }

    const bool sorted_order = (idx_W1 >= 0 && idx_Wp0 >= 0 && idx_W1 < idx_Wp0);
    const float* W_ih = sorted_order ? Wp1 : Wp0;
    const float* W_hh = sorted_order ? Wp0 : Wp1;

    float* out = (float*)d_out;

    k_table    <<<VOCAB_, 128>>>(emb, W_ih, b_ih, b_hh);
    k_lstm4    <<<B_ / 4, 128>>>(x, W_hh);
    k_ff2      <<<(T_ * B_) / 256, 256>>>(W1, b1, W2, b2, out);
    k_softmax2 <<<B_, 256>>>(out);
}